// round 8
// baseline (speedup 1.0000x reference)
#include <cuda_runtime.h>
#include <cuda_bf16.h>

// Problem constants
#define Bsz   128
#define Tlen  80
#define Edim  100
#define Udim  512

// Launch shape: 4 independent row-groups x 32 col-slice CTAs, 8 warps/CTA
#define NCTA  128
#define NTHR  256
#define NWARP 8
#define GSZ   32
#define NGRP  4
#define RPC   32
#define PADK  516

#define APAD  40            // phase-A reduction pad
#define BPAD  20            // phase-B reduction pad

// SMEM layout (float offsets)
#define OFF_WA 0                          // 32 cols x PADK
#define OFF_WB (32 * PADK)                // 16 cols x PADK
#define OFF_H  (OFF_WB + 16 * PADK)       // 32 rows x PADK
#define OFF_RED (OFF_H + RPC * PADK)      // 8 warps x 32 x APAD
#define SMEM_FLOATS (OFF_RED + NWARP * 32 * APAD)
#define SMEM_BYTES  (SMEM_FLOATS * 4)     // 206080 B

typedef unsigned long long u64;

// Device-global scratch (double-buffered h / h0)
__device__ float g_P0[Tlen * Bsz * Udim];
__device__ float g_hb [2][Bsz * Udim];
__device__ float g_h0b[2][Bsz * Udim];
__device__ float g_r1[Bsz * Udim];
__device__ unsigned g_fa[NGRP][GSZ];   // fa[j] = #completed A phases of CTA j
__device__ unsigned g_fb[NGRP][GSZ];   // fb[j] = #completed B phases

// ---------------- helpers ----------------

__device__ __forceinline__ u64 ffma2(u64 a, u64 b, u64 c) {
    u64 d;
    asm("fma.rn.f32x2 %0, %1, %2, %3;" : "=l"(d) : "l"(a), "l"(b), "l"(c));
    return d;
}

__device__ __forceinline__ float fsum(u64 v) {
    float lo, hi;
    asm("mov.b64 {%0, %1}, %2;" : "=f"(lo), "=f"(hi) : "l"(v));
    return lo + hi;
}

__device__ __forceinline__ float tanh_fast(float x) {
    float e = __expf(2.0f * x);
    return 1.0f - __fdividef(2.0f, e + 1.0f);
}

__device__ __forceinline__ void st_rel(unsigned* p, unsigned v) {
    asm volatile("st.release.gpu.global.u32 [%0], %1;" :: "l"(p), "r"(v) : "memory");
}
__device__ __forceinline__ unsigned ld_acq(const unsigned* p) {
    unsigned v;
    asm volatile("ld.acquire.gpu.global.u32 %0, [%1];" : "=r"(v) : "l"(p) : "memory");
    return v;
}

// Warp-converged wait: lanes 0..3 poll f[i0..i0+3] until all >= tgt.
__device__ __forceinline__ void wait4(const unsigned* f, int i0, unsigned tgt) {
    const int lane = threadIdx.x & 31;
    unsigned v = tgt;
    do {
        if (lane < 4) v = ld_acq(f + i0 + lane);
    } while (!__all_sync(0xffffffffu, v >= tgt));
}

// Warp-converged wait on 3 arbitrary flags.
__device__ __forceinline__ void wait3(const unsigned* f, int a, int b, int c, unsigned tgt) {
    const int lane = threadIdx.x & 31;
    const int idx = (lane == 0) ? a : (lane == 1) ? b : c;
    unsigned v = tgt;
    do {
        if (lane < 3) v = ld_acq(f + idx);
    } while (!__all_sync(0xffffffffu, v >= tgt));
}

// Warp w loads its own K-slice strip of H: 32 rows x 64 floats from src
// (row stride Udim) into HTw (row stride PADK). Coalesced LDG, conflict-free STS.
__device__ __forceinline__ void load_strip(float* HTw, const float* src) {
    const int lane = threadIdx.x & 31;
    const int sr = lane >> 4;        // row parity
    const int sq = lane & 15;        // float4 index within 64-float slice
    float4 tmp[16];
#pragma unroll
    for (int i = 0; i < 16; i++)
        tmp[i] = __ldcg((const float4*)(src + (2 * i + sr) * Udim) + sq);
#pragma unroll
    for (int i = 0; i < 16; i++)
        *(float4*)(HTw + (2 * i + sr) * PADK + sq * 4) = tmp[i];
    __syncwarp();
}

// ---------------- kernel 1: P0 = emb[tokens] @ k0 + b0 ----------------

#define PC_PAIRS 16
#define PTHR 128

__global__ void __launch_bounds__(PTHR) pre_kernel(
    const int* __restrict__ tokens, const float* __restrict__ emb,
    const float* __restrict__ k0, const float* __restrict__ b0)
{
    __shared__ int    tok[PC_PAIRS];
    __shared__ float2 xs2[PC_PAIRS][Edim];

    const int tid = threadIdx.x;

    if (blockIdx.x == 0 && tid < NGRP * GSZ) {
        ((unsigned*)g_fa)[tid] = 0u;
        ((unsigned*)g_fb)[tid] = 0u;
    }

    // zero g_hb[0] (initial hidden state)
    if (blockIdx.x < 64) {
        int base = blockIdx.x * 1024 + tid * 8;
        float4 z = make_float4(0.f, 0.f, 0.f, 0.f);
        *(float4*)(&g_hb[0][base])     = z;
        *(float4*)(&g_hb[0][base + 4]) = z;
    }

    const int pbase = blockIdx.x * PC_PAIRS;
    if (tid < PC_PAIRS) tok[tid] = tokens[pbase + tid];
    __syncthreads();

    for (int e = tid; e < PC_PAIRS * Edim; e += PTHR) {
        int p = e / Edim, k = e - p * Edim;
        float v = emb[tok[p] * Edim + k];
        xs2[p][k] = make_float2(v, v);
    }
    __syncthreads();

    const int u = tid * 4;
    u64 acc[PC_PAIRS][2];
#pragma unroll
    for (int p = 0; p < PC_PAIRS; p++) { acc[p][0] = 0ull; acc[p][1] = 0ull; }

    for (int k = 0; k < Edim; k++) {
        ulonglong2 wv = *(const ulonglong2*)(k0 + k * Udim + u);
#pragma unroll
        for (int p = 0; p < PC_PAIRS; p++) {
            u64 x2 = *(const u64*)&xs2[p][k];
            acc[p][0] = ffma2(x2, wv.x, acc[p][0]);
            acc[p][1] = ffma2(x2, wv.y, acc[p][1]);
        }
    }

    float4 bv = *(const float4*)(b0 + u);
#pragma unroll
    for (int p = 0; p < PC_PAIRS; p++) {
        int pi = pbase + p;
        int b = pi / Tlen;
        int t = pi - b * Tlen;
        float2 lo, hi;
        asm("mov.b64 {%0, %1}, %2;" : "=f"(lo.x), "=f"(lo.y) : "l"(acc[p][0]));
        asm("mov.b64 {%0, %1}, %2;" : "=f"(hi.x), "=f"(hi.y) : "l"(acc[p][1]));
        float4 o = make_float4(lo.x + bv.x, lo.y + bv.y, hi.x + bv.z, hi.y + bv.w);
        *(float4*)(g_P0 + ((size_t)(t * Bsz) + b) * Udim + u) = o;
    }
}

// ---------------- kernel 2: persistent scan, dataflow-synced ----------------
// CTA (g, j): g = row group (32 rows), j = col slice. 8 warps; warp w owns
// K-slice [64w, 64w+64). Selective producer waits (no global barrier):
//   A(t) warp w waits fb[4w..4w+3] >= t      (its h(t) strip ready)
//   B(t) warp w waits fa[2w], fa[2w+1], fa[16+(j>>1)] >= t+1
// g_hb / g_h0b double-buffered; WAR closure proven via transitive wait cones.

__global__ void __launch_bounds__(NTHR, 1) rnn_kernel(
    const float* __restrict__ rk0, const float* __restrict__ rk1,
    const float* __restrict__ k1,  const float* __restrict__ b1,
    const float* __restrict__ wd,  const float* __restrict__ bd,
    float* __restrict__ out)
{
    extern __shared__ float sm[];
    const int tid  = threadIdx.x;
    const int g    = blockIdx.x >> 5;
    const int j    = blockIdx.x & 31;
    const int r0   = g * RPC;
    const int w    = tid >> 5;
    const int lane = tid & 31;
    const bool isA0 = (j < 16);
    const int r1prod = 16 + (j >> 1);

    // --- load weight slices into SMEM (once), transposed [col][K] ---
    const float* wsrcA = isA0 ? rk0 : rk1;
    const int cbaseA = (j & 15) * 32;
    for (int e = tid; e < 32 * Udim; e += NTHR) {
        int k = e >> 5, cc = e & 31;
        sm[OFF_WA + cc * PADK + k] = wsrcA[k * Udim + cbaseA + cc];
    }
    const int cbaseB = j * 16;
    for (int e = tid; e < 16 * Udim; e += NTHR) {
        int k = e >> 4, cc = e & 15;
        sm[OFF_WB + cc * PADK + k] = k1[k * Udim + cbaseB + cc];
    }

    // warp FMA geometry
    const int rg  = lane & 3;
    const int cg  = lane >> 2;
    const int rgB = lane & 7;
    const int cgB = lane >> 3;

    // finalize geometry (256 threads)
    const int frow = tid >> 3;
    const int fcA  = (tid & 7) * 4;
    const int fcB  = (tid & 7) * 2;

    float4 b1v = make_float4(0.f, 0.f, 0.f, 0.f);
    if (!isA0) b1v = *(const float4*)(b1 + cbaseA + fcA);
    __syncthreads();

    const float* HpA = sm + OFF_H  + w * 64;
    float*       HTw = sm + OFF_H  + w * 64;
    const float* WpA = sm + OFF_WA + w * 64;
    const float* WpB = sm + OFF_WB + w * 64;
    float* redw  = sm + OFF_RED + w * 32 * APAD;
    float* redwB = sm + OFF_RED + w * 32 * BPAD;

    unsigned* fa = g_fa[g];
    unsigned* fb = g_fb[g];

    for (int t = 0; t < Tlen; t++) {
        // ================= Phase A: h @ [rk0 | rk1] =================
        float4 pv = make_float4(0.f, 0.f, 0.f, 0.f);
        if (isA0)   // static data: safe to prefetch before the wait
            pv = __ldcg((const float4*)(g_P0 + ((size_t)t * Bsz + r0 + frow) * Udim
                                        + cbaseA + fcA));

        wait4(fb, 4 * w, (unsigned)t);   // h(t) strip producers done

        load_strip(HTw, &g_hb[t & 1][0] + (size_t)r0 * Udim + 64 * w);

        u64 acc[8][4];
#pragma unroll
        for (int i = 0; i < 8; i++)
#pragma unroll
            for (int jj = 0; jj < 4; jj++) acc[i][jj] = 0ull;

#pragma unroll 2
        for (int kc = 0; kc < 16; kc++) {
            const int k = kc * 4;
            ulonglong2 Wv[4];
#pragma unroll
            for (int jj = 0; jj < 4; jj++)
                Wv[jj] = *(const ulonglong2*)(WpA + (cg + 8 * jj) * PADK + k);
#pragma unroll
            for (int i = 0; i < 8; i++) {
                ulonglong2 Hv = *(const ulonglong2*)(HpA + (rg + 4 * i) * PADK + k);
#pragma unroll
                for (int jj = 0; jj < 4; jj++) {
                    acc[i][jj] = ffma2(Hv.x, Wv[jj].x, acc[i][jj]);
                    acc[i][jj] = ffma2(Hv.y, Wv[jj].y, acc[i][jj]);
                }
            }
        }

#pragma unroll
        for (int i = 0; i < 8; i++)
#pragma unroll
            for (int jj = 0; jj < 4; jj++)
                redw[(rg + 4 * i) * APAD + cg + 8 * jj] = fsum(acc[i][jj]);
        __syncthreads();

        // finalize: 4 outputs/thread
        {
            float4 s = make_float4(0.f, 0.f, 0.f, 0.f);
#pragma unroll
            for (int p = 0; p < NWARP; p++) {
                float4 v = *(const float4*)(sm + OFF_RED + p * 32 * APAD
                                            + frow * APAD + fcA);
                s.x += v.x; s.y += v.y; s.z += v.z; s.w += v.w;
            }
            int grow = (r0 + frow) * Udim + cbaseA + fcA;
            if (isA0) {
                float4 o;
                o.x = tanh_fast(s.x + pv.x);
                o.y = tanh_fast(s.y + pv.y);
                o.z = tanh_fast(s.z + pv.z);
                o.w = tanh_fast(s.w + pv.w);
                *(float4*)(&g_h0b[t & 1][0] + grow) = o;
            } else {
                float4 o = make_float4(s.x + b1v.x, s.y + b1v.y,
                                       s.z + b1v.z, s.w + b1v.w);
                *(float4*)(g_r1 + grow) = o;
            }
        }
        __syncthreads();
        if (tid == 0) st_rel(&fa[j], (unsigned)(t + 1));

        // ================= Phase B: h0 @ k1 =================
        wait3(fa, 2 * w, 2 * w + 1, r1prod, (unsigned)(t + 1));

        float2 r1v = __ldcg((const float2*)(g_r1 + (size_t)(r0 + frow) * Udim
                                            + cbaseB + fcB));

        load_strip(HTw, &g_h0b[t & 1][0] + (size_t)r0 * Udim + 64 * w);

        u64 acc2[4][4];
#pragma unroll
        for (int i = 0; i < 4; i++)
#pragma unroll
            for (int jj = 0; jj < 4; jj++) acc2[i][jj] = 0ull;

#pragma unroll 2
        for (int kc = 0; kc < 16; kc++) {
            const int k = kc * 4;
            ulonglong2 Wv[4];
#pragma unroll
            for (int jj = 0; jj < 4; jj++)
                Wv[jj] = *(const ulonglong2*)(WpB + (cgB + 4 * jj) * PADK + k);
#pragma unroll
            for (int i = 0; i < 4; i++) {
                ulonglong2 Hv = *(const ulonglong2*)(HpA + (rgB + 8 * i) * PADK + k);
#pragma unroll
                for (int jj = 0; jj < 4; jj++) {
                    acc2[i][jj] = ffma2(Hv.x, Wv[jj].x, acc2[i][jj]);
                    acc2[i][jj] = ffma2(Hv.y, Wv[jj].y, acc2[i][jj]);
                }
            }
        }

#pragma unroll
        for (int i = 0; i < 4; i++)
#pragma unroll
            for (int jj = 0; jj < 4; jj++)
                redwB[(rgB + 8 * i) * BPAD + cgB + 4 * jj] = fsum(acc2[i][jj]);
        __syncthreads();

        // finalize: 2 outputs/thread
        {
            float2 s = make_float2(0.f, 0.f);
#pragma unroll
            for (int p = 0; p < NWARP; p++) {
                float2 v = *(const float2*)(sm + OFF_RED + p * 32 * BPAD
                                            + frow * BPAD + fcB);
                s.x += v.x; s.y += v.y;
            }
            int grow = (r0 + frow) * Udim + cbaseB + fcB;
            float2 o;
            o.x = tanh_fast(s.x + r1v.x);
            o.y = tanh_fast(s.y + r1v.y);
            *(float2*)(&g_hb[(t + 1) & 1][0] + grow) = o;
        }
        __syncthreads();
        if (tid == 0) st_rel(&fb[j], (unsigned)(t + 1));
    }

    // ---- output head: sigmoid(h @ wd + bd), CTA j==0 of each group ----
    if (j == 0) {
        // wait all 32 CTAs' final B done
        if (w == 0) {
            unsigned v;
            do { v = ld_acq(&fb[lane]); }
            while (!__all_sync(0xffffffffu, v >= (unsigned)Tlen));
        }
        __syncthreads();

        const float* hfin = &g_hb[Tlen & 1][0];
        int row = r0 + (tid >> 3);
        int p   = tid & 7;
        const float4* hv = (const float4*)(hfin + row * Udim + p * 64);
        const float4* wv = (const float4*)(wd + p * 64);
        float s = 0.f;
#pragma unroll
        for (int q = 0; q < 16; q++) {
            float4 a = __ldcg(hv + q);
            float4 b = wv[q];
            s += a.x * b.x + a.y * b.y + a.z * b.z + a.w * b.w;
        }
        s += __shfl_xor_sync(0xffffffffu, s, 1);
        s += __shfl_xor_sync(0xffffffffu, s, 2);
        s += __shfl_xor_sync(0xffffffffu, s, 4);
        if (p == 0) out[row] = 1.0f / (1.0f + __expf(-(s + bd[0])));
    }
}

// ---------------- launch ----------------

extern "C" void kernel_launch(void* const* d_in, const int* in_sizes, int n_in,
                              void* d_out, int out_size) {
    const int*   tokens = (const int*)  d_in[0];
    const float* emb    = (const float*)d_in[1];
    const float* k0     = (const float*)d_in[2];
    const float* rk0    = (const float*)d_in[3];
    const float* b0     = (const float*)d_in[4];
    const float* k1     = (const float*)d_in[5];
    const float* rk1    = (const float*)d_in[6];
    const float* b1     = (const float*)d_in[7];
    const float* wd     = (const float*)d_in[8];
    const float* bd     = (const float*)d_in[9];
    float* out = (float*)d_out;

    (void)in_sizes; (void)n_in; (void)out_size;

    cudaFuncSetAttribute(rnn_kernel, cudaFuncAttributeMaxDynamicSharedMemorySize, SMEM_BYTES);

    pre_kernel<<<(Bsz * Tlen) / PC_PAIRS, PTHR>>>(tokens, emb, k0, b0);
    rnn_kernel<<<NCTA, NTHR, SMEM_BYTES>>>(rk0, rk1, k1, b1, wd, bd, out);
}

// round 9
// speedup vs baseline: 2.1706x; 2.1706x over previous
#include <cuda_runtime.h>
#include <cuda_bf16.h>

// Problem constants
#define Bsz   128
#define Tlen  80
#define Edim  100
#define Udim  512

// Launch shape: 4 row-groups x 32 col-slice CTAs, 16 warps/CTA
#define NCTA  128
#define NTHR  512
#define GSZ   32
#define NGRP  4
#define RPC   32
#define PADK  516

#define APAD  40            // reduction pads: bank = 8*rg + cg (distinct)
#define BPAD  40

// SMEM layout (float offsets)
#define OFF_WA 0                          // 32 cols x PADK
#define OFF_WB (32 * PADK)                // 16 cols x PADK
#define OFF_H  (OFF_WB + 16 * PADK)       // 32 rows x PADK
#define OFF_RED (OFF_H + RPC * PADK)      // 8 K-slices x 32 x APAD
#define SMEM_FLOATS (OFF_RED + 8 * 32 * APAD)
#define SMEM_BYTES  (SMEM_FLOATS * 4)     // 206080 B

typedef unsigned long long u64;

// Device-global scratch
__device__ float g_P0[Tlen * Bsz * Udim];
__device__ float g_h [Bsz * Udim];
__device__ float g_h0[Bsz * Udim];
__device__ float g_r1[Bsz * Udim];
__device__ unsigned g_ctr[NGRP * 128];      // one counter per group, 512B apart

// ---------------- helpers ----------------

__device__ __forceinline__ u64 ffma2(u64 a, u64 b, u64 c) {
    u64 d;
    asm("fma.rn.f32x2 %0, %1, %2, %3;" : "=l"(d) : "l"(a), "l"(b), "l"(c));
    return d;
}

__device__ __forceinline__ float fsum(u64 v) {
    float lo, hi;
    asm("mov.b64 {%0, %1}, %2;" : "=f"(lo), "=f"(hi) : "l"(v));
    return lo + hi;
}

__device__ __forceinline__ float tanh_fast(float x) {
    float e = __expf(2.0f * x);
    return 1.0f - __fdividef(2.0f, e + 1.0f);
}

// Group barrier (R4-proven): monotonic counter, release-red arrive +
// acquire-load poll by ONE thread per CTA.
__device__ __forceinline__ void gbar(unsigned* ctr, unsigned target) {
    __syncthreads();
    if (threadIdx.x == 0) {
        asm volatile("red.release.gpu.global.add.u32 [%0], %1;"
                     :: "l"(ctr), "r"(1u) : "memory");
        unsigned v;
        do {
            asm volatile("ld.acquire.gpu.global.u32 %0, [%1];"
                         : "=r"(v) : "l"(ctr) : "memory");
        } while (v < target);
    }
    __syncthreads();
}

// Warp (q,h) loads its 16-row x 64-float strip: src rows have stride Udim,
// dest rows stride PADK. Lanes: sr=lane>>4 row parity, sq=lane&15 float4 idx.
// Coalesced LDG (2 rows x 256B per instr); STS hits 4-wavefront floor.
__device__ __forceinline__ void load_strip16(float* HT, const float* src) {
    const int lane = threadIdx.x & 31;
    const int sr = lane >> 4;
    const int sq = lane & 15;
    float4 tmp[8];
#pragma unroll
    for (int i = 0; i < 8; i++)
        tmp[i] = __ldcg((const float4*)(src + (2 * i + sr) * Udim) + sq);
#pragma unroll
    for (int i = 0; i < 8; i++)
        *(float4*)(HT + (2 * i + sr) * PADK + sq * 4) = tmp[i];
    __syncwarp();
}

// ---------------- kernel 1: P0 = emb[tokens] @ k0 + b0 ----------------

#define PC_PAIRS 16
#define PTHR 128

__global__ void __launch_bounds__(PTHR) pre_kernel(
    const int* __restrict__ tokens, const float* __restrict__ emb,
    const float* __restrict__ k0, const float* __restrict__ b0)
{
    __shared__ int    tok[PC_PAIRS];
    __shared__ float2 xs2[PC_PAIRS][Edim];

    const int tid = threadIdx.x;

    if (blockIdx.x == 0 && tid < NGRP) g_ctr[tid * 128] = 0;

    if (blockIdx.x < 64) {
        int base = blockIdx.x * 1024 + tid * 8;
        float4 z = make_float4(0.f, 0.f, 0.f, 0.f);
        *(float4*)(g_h + base)     = z;
        *(float4*)(g_h + base + 4) = z;
    }

    const int pbase = blockIdx.x * PC_PAIRS;
    if (tid < PC_PAIRS) tok[tid] = tokens[pbase + tid];
    __syncthreads();

    for (int e = tid; e < PC_PAIRS * Edim; e += PTHR) {
        int p = e / Edim, k = e - p * Edim;
        float v = emb[tok[p] * Edim + k];
        xs2[p][k] = make_float2(v, v);
    }
    __syncthreads();

    const int u = tid * 4;
    u64 acc[PC_PAIRS][2];
#pragma unroll
    for (int p = 0; p < PC_PAIRS; p++) { acc[p][0] = 0ull; acc[p][1] = 0ull; }

    for (int k = 0; k < Edim; k++) {
        ulonglong2 wv = *(const ulonglong2*)(k0 + k * Udim + u);
#pragma unroll
        for (int p = 0; p < PC_PAIRS; p++) {
            u64 x2 = *(const u64*)&xs2[p][k];
            acc[p][0] = ffma2(x2, wv.x, acc[p][0]);
            acc[p][1] = ffma2(x2, wv.y, acc[p][1]);
        }
    }

    float4 bv = *(const float4*)(b0 + u);
#pragma unroll
    for (int p = 0; p < PC_PAIRS; p++) {
        int pi = pbase + p;
        int b = pi / Tlen;
        int t = pi - b * Tlen;
        float2 lo, hi;
        asm("mov.b64 {%0, %1}, %2;" : "=f"(lo.x), "=f"(lo.y) : "l"(acc[p][0]));
        asm("mov.b64 {%0, %1}, %2;" : "=f"(hi.x), "=f"(hi.y) : "l"(acc[p][1]));
        float4 o = make_float4(lo.x + bv.x, lo.y + bv.y, hi.x + bv.z, hi.y + bv.w);
        *(float4*)(g_P0 + ((size_t)(t * Bsz) + b) * Udim + u) = o;
    }
}

// ---------------- kernel 2: persistent scan ----------------
// CTA (g, j): g = row group (32 rows), j = col slice. 16 warps:
//   q = w>>1 : K-slice [64q, 64q+64) ; h = w&1 : rows [16h, 16h+16).
// Each warp: load own strip -> FMA -> store partials to buffer q.
// 8 partial buffers (pairs write disjoint rows). R4 group barrier x2/step.
// Phase A warp tile 16x32 (thread 4x4): rows rg+4i+16h, cols cg+8jj.
// Phase B warp tile 16x16 (thread 4x2): rows rg+4i+16h, cols cg+8jj (jj<2).

__global__ void __launch_bounds__(NTHR, 1) rnn_kernel(
    const float* __restrict__ rk0, const float* __restrict__ rk1,
    const float* __restrict__ k1,  const float* __restrict__ b1,
    const float* __restrict__ wd,  const float* __restrict__ bd,
    float* __restrict__ out)
{
    extern __shared__ float sm[];
    const int tid  = threadIdx.x;
    const int g    = blockIdx.x >> 5;
    const int j    = blockIdx.x & 31;
    const int r0   = g * RPC;
    const int w    = tid >> 5;
    const int lane = tid & 31;
    const int q    = w >> 1;          // K-slice
    const int hh   = w & 1;           // row half
    const bool isA0 = (j < 16);

    unsigned* ctr = g_ctr + g * 128;
    unsigned nbar = 0;

    // --- load weight slices into SMEM (once), transposed [col][K] ---
    const float* wsrcA = isA0 ? rk0 : rk1;
    const int cbaseA = (j & 15) * 32;
    for (int e = tid; e < 32 * Udim; e += NTHR) {
        int k = e >> 5, cc = e & 31;
        sm[OFF_WA + cc * PADK + k] = wsrcA[k * Udim + cbaseA + cc];
    }
    const int cbaseB = j * 16;
    for (int e = tid; e < 16 * Udim; e += NTHR) {
        int k = e >> 4, cc = e & 15;
        sm[OFF_WB + cc * PADK + k] = k1[k * Udim + cbaseB + cc];
    }

    // FMA lane geometry
    const int rg = lane & 3;          // + 4i + 16h -> rows
    const int cg = lane >> 2;         // + 8jj -> cols

    // finalize geometry (512 threads)
    const int frow = tid >> 4;            // 0..31
    const int fcA  = (tid & 15) * 2;      // phase-A: 2 cols
    const int fcB  = tid & 15;            // phase-B: 1 col

    float2 b1v = make_float2(0.f, 0.f);
    if (!isA0) b1v = *(const float2*)(b1 + cbaseA + fcA);
    __syncthreads();

    const float* Hp  = sm + OFF_H  + q * 64;   // K-slice base (FMA reads)
    float*       HTw = sm + OFF_H  + hh * 16 * PADK + q * 64;  // strip dest
    const float* WpA = sm + OFF_WA + q * 64;
    const float* WpB = sm + OFF_WB + q * 64;
    float* redq = sm + OFF_RED + q * 32 * APAD;

    const int rowbase = hh * 16;

    for (int t = 0; t < Tlen; t++) {
        // ================= Phase A: h @ [rk0 | rk1] =================
        float2 pv = make_float2(0.f, 0.f);
        if (isA0)
            pv = __ldcg((const float2*)(g_P0 + ((size_t)t * Bsz + r0 + frow) * Udim
                                        + cbaseA + fcA));

        load_strip16(HTw, g_h + (size_t)(r0 + rowbase) * Udim + 64 * q);

        u64 acc[4][4];
#pragma unroll
        for (int i = 0; i < 4; i++)
#pragma unroll
            for (int jj = 0; jj < 4; jj++) acc[i][jj] = 0ull;

#pragma unroll 2
        for (int kc = 0; kc < 16; kc++) {
            const int k = kc * 4;
            ulonglong2 Wv[4];
#pragma unroll
            for (int jj = 0; jj < 4; jj++)
                Wv[jj] = *(const ulonglong2*)(WpA + (cg + 8 * jj) * PADK + k);
#pragma unroll
            for (int i = 0; i < 4; i++) {
                ulonglong2 Hv = *(const ulonglong2*)(Hp + (rowbase + rg + 4 * i) * PADK + k);
#pragma unroll
                for (int jj = 0; jj < 4; jj++) {
                    acc[i][jj] = ffma2(Hv.x, Wv[jj].x, acc[i][jj]);
                    acc[i][jj] = ffma2(Hv.y, Wv[jj].y, acc[i][jj]);
                }
            }
        }

        // partials: bank = 8*rg + cg (+consts) -> conflict-free
#pragma unroll
        for (int i = 0; i < 4; i++)
#pragma unroll
            for (int jj = 0; jj < 4; jj++)
                redq[(rowbase + rg + 4 * i) * APAD + cg + 8 * jj] = fsum(acc[i][jj]);
        __syncthreads();

        // finalize: 2 outputs/thread (float2 over 8 K-slice partials)
        {
            float2 s = make_float2(0.f, 0.f);
#pragma unroll
            for (int p = 0; p < 8; p++) {
                float2 v = *(const float2*)(sm + OFF_RED + p * 32 * APAD
                                            + frow * APAD + fcA);
                s.x += v.x; s.y += v.y;
            }
            int grow = (r0 + frow) * Udim + cbaseA + fcA;
            if (isA0) {
                float2 o;
                o.x = tanh_fast(s.x + pv.x);
                o.y = tanh_fast(s.y + pv.y);
                *(float2*)(g_h0 + grow) = o;
            } else {
                *(float2*)(g_r1 + grow) = make_float2(s.x + b1v.x, s.y + b1v.y);
            }
        }
        nbar++; gbar(ctr, nbar * GSZ);

        // ================= Phase B: h0 @ k1 =================
        float r1v = __ldcg(g_r1 + (size_t)(r0 + frow) * Udim + cbaseB + fcB);

        load_strip16(HTw, g_h0 + (size_t)(r0 + rowbase) * Udim + 64 * q);

        u64 acc2[4][2];
#pragma unroll
        for (int i = 0; i < 4; i++) { acc2[i][0] = 0ull; acc2[i][1] = 0ull; }

#pragma unroll 2
        for (int kc = 0; kc < 16; kc++) {
            const int k = kc * 4;
            ulonglong2 Wv[2];
#pragma unroll
            for (int jj = 0; jj < 2; jj++)
                Wv[jj] = *(const ulonglong2*)(WpB + (cg + 8 * jj) * PADK + k);
#pragma unroll
            for (int i = 0; i < 4; i++) {
                ulonglong2 Hv = *(const ulonglong2*)(Hp + (rowbase + rg + 4 * i) * PADK + k);
#pragma unroll
                for (int jj = 0; jj < 2; jj++) {
                    acc2[i][jj] = ffma2(Hv.x, Wv[jj].x, acc2[i][jj]);
                    acc2[i][jj] = ffma2(Hv.y, Wv[jj].y, acc2[i][jj]);
                }
            }
        }

        // partials: 16 cols, BPAD=40 -> bank = 8*rg + cg (+consts)
#pragma unroll
        for (int i = 0; i < 4; i++)
#pragma unroll
            for (int jj = 0; jj < 2; jj++)
                redq[(rowbase + rg + 4 * i) * BPAD + cg + 8 * jj] = fsum(acc2[i][jj]);
        __syncthreads();

        // finalize: 1 output/thread
        {
            float s = 0.f;
#pragma unroll
            for (int p = 0; p < 8; p++)
                s += sm[OFF_RED + p * 32 * BPAD + frow * BPAD + fcB];
            g_h[(r0 + frow) * Udim + cbaseB + fcB] = tanh_fast(s + r1v);
        }
        nbar++; gbar(ctr, nbar * GSZ);
    }

    // ---- output head: sigmoid(h @ wd + bd), CTA j==0 of each group ----
    if (j == 0) {
        int row = r0 + (tid >> 4);        // 32 rows, 16 threads each
        int p   = tid & 15;
        const float4* hv = (const float4*)(g_h + row * Udim + p * 32);
        const float4* wv = (const float4*)(wd + p * 32);
        float s = 0.f;
#pragma unroll
        for (int qq = 0; qq < 8; qq++) {
            float4 a = __ldcg(hv + qq);
            float4 b = wv[qq];
            s += a.x * b.x + a.y * b.y + a.z * b.z + a.w * b.w;
        }
        s += __shfl_xor_sync(0xffffffffu, s, 1);
        s += __shfl_xor_sync(0xffffffffu, s, 2);
        s += __shfl_xor_sync(0xffffffffu, s, 4);
        s += __shfl_xor_sync(0xffffffffu, s, 8);
        if (p == 0) out[row] = 1.0f / (1.0f + __expf(-(s + bd[0])));
    }
}

// ---------------- launch ----------------

extern "C" void kernel_launch(void* const* d_in, const int* in_sizes, int n_in,
                              void* d_out, int out_size) {
    const int*   tokens = (const int*)  d_in[0];
    const float* emb    = (const float*)d_in[1];
    const float* k0     = (const float*)d_in[2];
    const float* rk0    = (const float*)d_in[3];
    const float* b0     = (const float*)d_in[4];
    const float* k1     = (const float*)d_in[5];
    const float* rk1    = (const float*)d_in[6];
    const float* b1     = (const float*)d_in[7];
    const float* wd     = (const float*)d_in[8];
    const float* bd     = (const float*)d_in[9];
    float* out = (float*)d_out;

    (void)in_sizes; (void)n_in; (void)out_size;

    cudaFuncSetAttribute(rnn_kernel, cudaFuncAttributeMaxDynamicSharedMemorySize, SMEM_BYTES);

    pre_kernel<<<(Bsz * Tlen) / PC_PAIRS, PTHR>>>(tokens, emb, k0, b0);
    rnn_kernel<<<NCTA, NTHR, SMEM_BYTES>>>(rk0, rk1, k1, b1, wd, bd, out);
}